// round 1
// baseline (speedup 1.0000x reference)
#include <cuda_runtime.h>
#include <math.h>

// ---------------- problem constants ----------------
#define BSZ    128
#define DIN    512
#define DMODEL 2048
#define MEMN   25
#define HIDN   32
#define NSY    256
#define NSYNC  32896        // 256*257/2
#define OUTD   1000
#define NITER  24
#define DK     (DIN + DMODEL)   // 2560
#define N1     (2 * DMODEL)     // 4096
#define SPLITK 16
#define KCHUNK (NSYNC / SPLITK) // 2056, divisible by 8
#define PRED_OFF 0
#define CERT_OFF (BSZ * OUTD * NITER)

// ---------------- persistent scratch (device globals, no allocs) ----------------
__device__ float g_trace[BSZ * DMODEL * MEMN];   // [b][d][m] circular, 26.2 MB
__device__ float g_actT [DMODEL * BSZ];          // [d][b] column-major activations
__device__ float g_z    [BSZ * N1];              // synapse pre-GLU output
__device__ float g_alpha[NSYNC * BSZ];           // [p][b]
__device__ float g_sync [NSYNC * BSZ];           // [p][b]
__device__ float g_r    [NSYNC];
__device__ int   g_pi   [NSYNC];
__device__ int   g_pj   [NSYNC];
__device__ float g_partial[SPLITK * BSZ * OUTD]; // split-K partials

__device__ __forceinline__ float sigmoidf_(float x) {
    return 1.0f / (1.0f + expf(-x));
}

// ---------------- init kernels (run every launch; deterministic) ----------------
__global__ void k_init_pairs(const float* __restrict__ decay) {
    int p = blockIdx.x * 256 + threadIdx.x;
    if (p >= NSYNC) return;
    // invert S(i) = i*NSY - i*(i-1)/2  (row starts of triu incl. diagonal)
    float pf = (float)p;
    int i = (int)floorf(256.5f - sqrtf(256.5f * 256.5f - 2.0f * pf));
    if (i < 0) i = 0;
    if (i > NSY - 1) i = NSY - 1;
    while (i > 0 && (i * NSY - i * (i - 1) / 2) > p) i--;
    while (i < NSY - 1 && ((i + 1) * NSY - (i + 1) * i / 2) <= p) i++;
    int Si = i * NSY - i * (i - 1) / 2;
    g_pi[p] = i;
    g_pj[p] = i + (p - Si);
    float d = fminf(fmaxf(decay[p], 0.0f), 15.0f);
    g_r[p] = expf(-d);
}

__global__ void k_init_trace(const float* __restrict__ st) {
    int idx = blockIdx.x * 256 + threadIdx.x;
    if (idx >= BSZ * DMODEL * MEMN) return;
    int m = idx % MEMN;
    int d = (idx / MEMN) % DMODEL;
    g_trace[idx] = st[d * MEMN + m];
}

__global__ void k_init_act(const float* __restrict__ sas) {
    int idx = blockIdx.x * 256 + threadIdx.x;
    if (idx >= DMODEL * BSZ) return;
    g_actT[idx] = sas[idx >> 7];   // [d][b], b = low 7 bits
}

__global__ void k_init_alpha(const float* __restrict__ sas,
                             const int* __restrict__ il,
                             const int* __restrict__ ir) {
    int p = blockIdx.x;
    int b = threadIdx.x;
    float v = sas[il[g_pi[p]]] * sas[ir[g_pj[p]]];
    g_alpha[p * BSZ + b] = v;
}

// ---------------- K1: synapse GEMM  z = [x|act] @ syn_w + syn_b ----------------
// M=128, K=2560, N=4096. BM=BN=64, BK=8, 256 thr, 4x4 thread tile.
__global__ __launch_bounds__(256) void k_gemm1(const float* __restrict__ x,
                                               const float* __restrict__ syn_w,
                                               const float* __restrict__ syn_b) {
    __shared__ float As[8][64];
    __shared__ float Bs[8][64];
    int n0 = blockIdx.x * 64;
    int m0 = blockIdx.y * 64;
    int tid = threadIdx.x;
    int tx = tid & 15, ty = tid >> 4;
    float acc[4][4] = {};
    int ml = tid & 63;
    int kq = tid >> 6;   // 0..3
    for (int k0 = 0; k0 < DK; k0 += 8) {
#pragma unroll
        for (int u = 0; u < 2; u++) {
            int kk = kq + u * 4;
            int k = k0 + kk;
            int gm = m0 + ml;
            float v;
            if (k < DIN) v = x[gm * DIN + k];
            else         v = g_actT[(k - DIN) * BSZ + gm];
            As[kk][ml] = v;
            Bs[kk][ml] = syn_w[k * N1 + n0 + ml];
        }
        __syncthreads();
#pragma unroll
        for (int kk = 0; kk < 8; kk++) {
            float a[4], b[4];
#pragma unroll
            for (int i = 0; i < 4; i++) a[i] = As[kk][ty * 4 + i];
#pragma unroll
            for (int j = 0; j < 4; j++) b[j] = Bs[kk][tx * 4 + j];
#pragma unroll
            for (int i = 0; i < 4; i++)
#pragma unroll
                for (int j = 0; j < 4; j++) acc[i][j] += a[i] * b[j];
        }
        __syncthreads();
    }
#pragma unroll
    for (int i = 0; i < 4; i++)
#pragma unroll
        for (int j = 0; j < 4; j++) {
            int gn = n0 + tx * 4 + j;
            g_z[(m0 + ty * 4 + i) * N1 + gn] = acc[i][j] + syn_b[gn];
        }
}

// ---------------- K2: GLU + LayerNorm -> write into trace slot ----------------
__global__ __launch_bounds__(256) void k_glu_ln(const float* __restrict__ ln_g,
                                                const float* __restrict__ ln_b,
                                                int slot) {
    int b = blockIdx.x;
    int tid = threadIdx.x;
    __shared__ float sv[DMODEL];
    __shared__ float red[256];
    float s1 = 0.f, s2 = 0.f;
    for (int d = tid; d < DMODEL; d += 256) {
        float a  = g_z[b * N1 + d];
        float bb = g_z[b * N1 + DMODEL + d];
        float v = a * sigmoidf_(bb);
        sv[d] = v;
        s1 += v;
        s2 += v * v;
    }
    red[tid] = s1; __syncthreads();
    for (int s = 128; s > 0; s >>= 1) { if (tid < s) red[tid] += red[tid + s]; __syncthreads(); }
    float mu = red[0] / (float)DMODEL;
    __syncthreads();
    red[tid] = s2; __syncthreads();
    for (int s = 128; s > 0; s >>= 1) { if (tid < s) red[tid] += red[tid + s]; __syncthreads(); }
    float var = red[0] / (float)DMODEL - mu * mu;
    float inv = rsqrtf(var + 1e-5f);
    for (int d = tid; d < DMODEL; d += 256) {
        float st = (sv[d] - mu) * inv * ln_g[d] + ln_b[d];
        g_trace[(b * DMODEL + d) * MEMN + slot] = st;
    }
}

// ---------------- K3: trace_proc (per-d MLP over MEM) -> act ----------------
__global__ __launch_bounds__(128) void k_traceproc(const float* __restrict__ w1,
                                                   const float* __restrict__ b1,
                                                   const float* __restrict__ w2,
                                                   const float* __restrict__ b2,
                                                   int t) {
    int d = blockIdx.x;
    int b = threadIdx.x;   // 128 threads = batch
    __shared__ float w1s[MEMN][64];
    __shared__ float b1s[64];
    __shared__ float w2s[32][2];
    __shared__ float b2s[2];
    for (int idx = b; idx < MEMN * 64; idx += 128) {
        int m = idx / 64, h = idx % 64;
        w1s[m][h] = w1[(m * 64 + h) * DMODEL + d];
    }
    if (b < 64) b1s[b] = b1[d * 64 + b];
    if (b < 64) { int h = b >> 1, o = b & 1; w2s[h][o] = w2[(h * 2 + o) * DMODEL + d]; }
    if (b < 2)  b2s[b] = b2[d * 2 + b];
    __syncthreads();

    float tr[MEMN];
    const float* tp = &g_trace[(b * DMODEL + d) * MEMN];
    int base = (t + 1) % MEMN;
#pragma unroll
    for (int m = 0; m < MEMN; m++) {
        int ph = base + m;
        if (ph >= MEMN) ph -= MEMN;
        tr[m] = tp[ph];
    }
    float o0 = b2s[0], o1 = b2s[1];
#pragma unroll
    for (int hh = 0; hh < 32; hh++) {
        float pa = b1s[hh], pb = b1s[hh + 32];
#pragma unroll
        for (int m = 0; m < MEMN; m++) {
            pa += tr[m] * w1s[m][hh];
            pb += tr[m] * w1s[m][hh + 32];
        }
        float h = pa * sigmoidf_(pb);
        o0 += h * w2s[hh][0];
        o1 += h * w2s[hh][1];
    }
    g_actT[d * BSZ + b] = o0 * sigmoidf_(o1);
}

// ---------------- K4: pairwise + alpha update + sync ----------------
__global__ __launch_bounds__(256) void k_syncpair(const int* __restrict__ il,
                                                  const int* __restrict__ ir,
                                                  int t) {
    int p = blockIdx.x * 2 + threadIdx.y;
    int b = threadIdx.x;
    int i = g_pi[p], j = g_pj[p];
    float l  = g_actT[il[i] * BSZ + b];
    float rr = g_actT[ir[j] * BSZ + b];
    float r = g_r[p];
    float a = g_alpha[p * BSZ + b];
    a = r * a + l * rr;
    g_alpha[p * BSZ + b] = a;
    float beta = 1.0f;
    for (int k = 0; k <= t; k++) beta = r * beta + 1.0f;
    g_sync[p * BSZ + b] = a / sqrtf(beta);
}

// ---------------- K5: output GEMM (split-K) ----------------
// pred = sync[128 x 32896] @ out_w[32896 x 1000]; sync stored [p][b].
__global__ __launch_bounds__(256) void k_gemm2(const float* __restrict__ W) {
    __shared__ float As[8][64];
    __shared__ float Bs[8][64];
    int n0 = blockIdx.x * 64;
    int m0 = blockIdx.y * 64;
    int kbeg = blockIdx.z * KCHUNK;
    int tid = threadIdx.x;
    int tx = tid & 15, ty = tid >> 4;
    float acc[4][4] = {};
    int ml = tid & 63;
    int kq = tid >> 6;
    for (int k0 = 0; k0 < KCHUNK; k0 += 8) {
#pragma unroll
        for (int u = 0; u < 2; u++) {
            int kk = kq + u * 4;
            int k = kbeg + k0 + kk;
            As[kk][ml] = g_sync[k * BSZ + m0 + ml];
            int gn = n0 + ml;
            Bs[kk][ml] = (gn < OUTD) ? W[k * OUTD + gn] : 0.0f;
        }
        __syncthreads();
#pragma unroll
        for (int kk = 0; kk < 8; kk++) {
            float a[4], b[4];
#pragma unroll
            for (int i = 0; i < 4; i++) a[i] = As[kk][ty * 4 + i];
#pragma unroll
            for (int j = 0; j < 4; j++) b[j] = Bs[kk][tx * 4 + j];
#pragma unroll
            for (int i = 0; i < 4; i++)
#pragma unroll
                for (int j = 0; j < 4; j++) acc[i][j] += a[i] * b[j];
        }
        __syncthreads();
    }
#pragma unroll
    for (int i = 0; i < 4; i++)
#pragma unroll
        for (int j = 0; j < 4; j++) {
            int gn = n0 + tx * 4 + j;
            if (gn < OUTD)
                g_partial[(blockIdx.z * BSZ + m0 + ty * 4 + i) * OUTD + gn] = acc[i][j];
        }
}

// ---------------- K6: split-K reduce + bias + write preds + entropy ----------------
__global__ __launch_bounds__(256) void k_finish(const float* __restrict__ outb,
                                                float* __restrict__ dout,
                                                int t) {
    int b = blockIdx.x;
    int tid = threadIdx.x;
    __shared__ float sp[OUTD];
    __shared__ float red[256];
    for (int n = tid; n < OUTD; n += 256) {
        float v = outb[n];
#pragma unroll
        for (int s = 0; s < SPLITK; s++) v += g_partial[(s * BSZ + b) * OUTD + n];
        sp[n] = v;
        dout[PRED_OFF + (b * OUTD + n) * NITER + t] = v;
    }
    __syncthreads();
    // max
    float mx = -3.4e38f;
    for (int n = tid; n < OUTD; n += 256) mx = fmaxf(mx, sp[n]);
    red[tid] = mx; __syncthreads();
    for (int s = 128; s > 0; s >>= 1) { if (tid < s) red[tid] = fmaxf(red[tid], red[tid + s]); __syncthreads(); }
    float smax = red[0];
    __syncthreads();
    // sum exp
    float se = 0.f;
    for (int n = tid; n < OUTD; n += 256) se += expf(sp[n] - smax);
    red[tid] = se; __syncthreads();
    for (int s = 128; s > 0; s >>= 1) { if (tid < s) red[tid] += red[tid + s]; __syncthreads(); }
    float lse = smax + logf(red[0]);
    __syncthreads();
    // entropy
    float ent = 0.f;
    for (int n = tid; n < OUTD; n += 256) {
        float lp = sp[n] - lse;
        ent += expf(lp) * lp;
    }
    red[tid] = ent; __syncthreads();
    for (int s = 128; s > 0; s >>= 1) { if (tid < s) red[tid] += red[tid + s]; __syncthreads(); }
    if (tid == 0) {
        float ne = -red[0] / logf(1000.0f);
        dout[CERT_OFF + (b * 2 + 0) * NITER + t] = ne;
        dout[CERT_OFF + (b * 2 + 1) * NITER + t] = 1.0f - ne;
    }
}

// ---------------- host ----------------
extern "C" void kernel_launch(void* const* d_in, const int* in_sizes, int n_in,
                              void* d_out, int out_size) {
    const float* x      = (const float*)d_in[0];
    const float* syn_w  = (const float*)d_in[1];
    const float* syn_b  = (const float*)d_in[2];
    const float* ln_g   = (const float*)d_in[3];
    const float* ln_b   = (const float*)d_in[4];
    const float* tp_w1  = (const float*)d_in[5];
    const float* tp_b1  = (const float*)d_in[6];
    const float* tp_w2  = (const float*)d_in[7];
    const float* tp_b2  = (const float*)d_in[8];
    const float* sas    = (const float*)d_in[9];
    const float* strc   = (const float*)d_in[10];
    const float* decay  = (const float*)d_in[11];
    const float* out_w  = (const float*)d_in[12];
    const float* out_b  = (const float*)d_in[13];
    const int*   il     = (const int*)d_in[14];
    const int*   ir     = (const int*)d_in[15];
    float* out = (float*)d_out;

    k_init_pairs<<<(NSYNC + 255) / 256, 256>>>(decay);
    k_init_trace<<<(BSZ * DMODEL * MEMN + 255) / 256, 256>>>(strc);
    k_init_act<<<(DMODEL * BSZ) / 256, 256>>>(sas);
    k_init_alpha<<<NSYNC, BSZ>>>(sas, il, ir);

    for (int t = 0; t < NITER; t++) {
        k_gemm1<<<dim3(N1 / 64, BSZ / 64), 256>>>(x, syn_w, syn_b);
        k_glu_ln<<<BSZ, 256>>>(ln_g, ln_b, t % MEMN);
        k_traceproc<<<DMODEL, BSZ>>>(tp_w1, tp_b1, tp_w2, tp_b2, t);
        k_syncpair<<<NSYNC / 2, dim3(BSZ, 2)>>>(il, ir, t);
        k_gemm2<<<dim3(16, 2, SPLITK), 256>>>(out_w);
        k_finish<<<BSZ, 256>>>(out_b, out, t);
    }
}